// round 15
// baseline (speedup 1.0000x reference)
#include <cuda_runtime.h>
#include <cuda_fp16.h>
#include <math.h>
#include <stdint.h>

// ---------------- problem constants ----------------
#define IN_DIM   768
#define HID      3072
#define BATCH    64
#define NCLS     6
#define NUM_PATCH 576
#define ATOMS    5
#define SEQ      (NCLS + NUM_PATCH)          // 582
#define M_PATCH  (BATCH * NUM_PATCH)         // 36864
#define M_CLS    (BATCH * NCLS)              // 384
#define M_ALL    (M_PATCH + M_CLS)           // 37248

// ---------------- device scratch ----------------
__device__ __half g_xh  [(size_t)M_ALL * IN_DIM];
__device__ __half g_w1t [(size_t)HID * IN_DIM];
__device__ __half g_hid [(size_t)M_ALL * HID];
__device__ __half g_w2t [(size_t)IN_DIM * HID];
__device__ __half g_wint [(size_t)ATOMS * HID * IN_DIM];
__device__ __half g_woutt[(size_t)ATOMS * IN_DIM * HID];
__device__ __half g_hm2 [(size_t)M_CLS * HID];
__device__ float g_e0  [(size_t)M_CLS * IN_DIM];
__device__ float g_moeOut[(size_t)M_CLS * 2 * IN_DIM];
__device__ int   g_cnt [ATOMS];                  // zero-init; final_mix re-zeroes
__device__ int   g_lst [ATOMS * M_CLS];
__device__ float g_wls [ATOMS * M_CLS];
__device__ int2  g_gI  [M_CLS];
__device__ float2 g_gW [M_CLS];

__device__ __forceinline__ float gelu_f(float v) {
    return 0.5f * v * (1.0f + erff(v * 0.7071067811865476f));
}

// ---------------- PTX helpers ----------------
__device__ __forceinline__ uint32_t smem_u32(const void* p) {
    uint32_t a;
    asm("{ .reg .u64 t; cvta.to.shared.u64 t, %1; cvt.u32.u64 %0, t; }" : "=r"(a) : "l"(p));
    return a;
}
__device__ __forceinline__ void cp16(uint32_t d, const void* s) {
    asm volatile("cp.async.cg.shared.global [%0], [%1], 16;" :: "r"(d), "l"(s));
}
#define CP_COMMIT()  asm volatile("cp.async.commit_group;" ::: "memory")
#define CP_WAIT(n)   asm volatile("cp.async.wait_group %0;" :: "n"(n) : "memory")

__device__ __forceinline__ void ldsm_x4(uint32_t& r0, uint32_t& r1, uint32_t& r2, uint32_t& r3,
                                        uint32_t addr) {
    asm volatile("ldmatrix.sync.aligned.m8n8.x4.shared.b16 {%0,%1,%2,%3}, [%4];"
                 : "=r"(r0), "=r"(r1), "=r"(r2), "=r"(r3) : "r"(addr));
}
__device__ __forceinline__ void mma_f16(float& c0, float& c1, float& c2, float& c3,
                                        uint32_t a0, uint32_t a1, uint32_t a2, uint32_t a3,
                                        uint32_t b0, uint32_t b1) {
    asm volatile("mma.sync.aligned.m16n8k16.row.col.f32.f16.f16.f32 "
                 "{%0,%1,%2,%3}, {%4,%5,%6,%7}, {%8,%9}, {%0,%1,%2,%3};"
                 : "+f"(c0), "+f"(c1), "+f"(c2), "+f"(c3)
                 : "r"(a0), "r"(a1), "r"(a2), "r"(a3), "r"(b0), "r"(b1));
}
__device__ __forceinline__ uint32_t sw128(uint32_t off) {
    return off ^ ((off >> 3) & 0x70);
}

// 128-thread 32x32 transpose tile: W[K,N] fp32 -> Wt[N,K] fp16
__device__ __forceinline__ void transpose_tile_128(const float* __restrict__ W,
                                                   __half* __restrict__ Wt,
                                                   int K, int N, int tileIdx,
                                                   char* smemRaw, int tid)
{
    float (*t)[33] = reinterpret_cast<float(*)[33]>(smemRaw);
    const int ktiles = K / 32;
    int k0 = (tileIdx % ktiles) * 32, n0 = (tileIdx / ktiles) * 32;
    int tx = tid & 31, ty = tid >> 5;            // ty 0..3
    #pragma unroll
    for (int i = 0; i < 8; i++)
        t[ty + i * 4][tx] = W[(size_t)(k0 + ty + i * 4) * N + n0 + tx];
    __syncthreads();
    #pragma unroll
    for (int it = 0; it < 4; it++) {
        int item = it * 128 + tid;               // 512 half2 items
        int n  = n0 + (item >> 4);
        int kp = (item & 15) * 2;
        __half2 hv;
        hv.x = __float2half(t[kp][item >> 4]);
        hv.y = __float2half(t[kp + 1][item >> 4]);
        *reinterpret_cast<__half2*>(Wt + (size_t)n * K + k0 + kp) = hv;
    }
}

// ---------------- fused GEMM phase kernels ----------------
#define BM 128
#define BN 128
#define BK 64
#define STAGES 3
#define STG_BYTES (BM * 128)
#define SMEM_DYN (STAGES * 2 * STG_BYTES)        // 96 KB
#define NTHREADS 128

#define A_NBX    (HID / BN)                      // 24
#define A_NBIG   (A_NBX * (M_ALL / BM))          // 6984
#define B_NBX    (IN_DIM / BN)                   // 6
#define B_NBIG   (B_NBX * (M_ALL / BM))          // 1746

#define GBM 64
#define GBN 128
#define GSTG_A (GBM * 128)
#define GSTG_B (GBN * 128)
#define GSTG (GSTG_A + GSTG_B)
#define HM_BLOCKS  (6 * (HID / GBN))             // 144
#define MOE_BLOCKS (ATOMS * 6 * (IN_DIM / GBN))  // 180

#define WT_W1    (IN_DIM / 32 * (HID / 32))      // 2304
#define WT_W2    (HID / 32 * (IN_DIM / 32))      // 2304
#define WT_WIN   (WT_W1 * ATOMS)                 // 11520
#define WT_WOUT  (WT_W2 * ATOMS)                 // 11520

// phase A extra ranges: gather(hm2) | W2 transpose | Wout transpose | gate
#define A_R0 A_NBIG                              // gather start
#define A_R1 (A_R0 + HM_BLOCKS)                  // w2t start
#define A_R2 (A_R1 + WT_W2)                      // woutt start
#define A_R3 (A_R2 + WT_WOUT)                    // gate start
#define A_TOTAL (A_R3 + M_CLS)                   // 21720
#define B_TOTAL (B_NBIG + MOE_BLOCKS)            // 1926

template<int PHASE>
__global__ __launch_bounds__(NTHREADS, 2)
void fused_gemm(const __half* __restrict__ A,
                const __half* __restrict__ Bw,
                const float* __restrict__ bias,
                __half* __restrict__ outH,
                float* __restrict__ outF,
                float* __restrict__ outE0,
                const __half* __restrict__ Ag,
                const __half* __restrict__ Wsm,
                const float* __restrict__ biasSm,
                __half* __restrict__ outGH,
                float* __restrict__ outGF,
                int* __restrict__ cnt,
                int* __restrict__ lst,
                float* __restrict__ wls,
                // phase-A-only migrated prologue work:
                const float* __restrict__ W2raw, __half* __restrict__ w2t,
                const float* __restrict__ WoutRaw, __half* __restrict__ woutt,
                const float* __restrict__ x, const float* __restrict__ Wg,
                int2* __restrict__ gI, float2* __restrict__ gW)
{
    extern __shared__ char smem[];
    const uint32_t sb = smem_u32(smem);
    const int tid  = threadIdx.x;
    const int wid  = tid >> 5, lane = tid & 31;
    const int NBIG = (PHASE == 0) ? A_NBIG : B_NBIG;
    const int K    = (PHASE == 0) ? IN_DIM : HID;
    const int C    = K >> 6;

    if (PHASE == 0 && blockIdx.x >= (unsigned)A_R1) {
        // ---------------- migrated prologue blocks ----------------
        if (blockIdx.x < (unsigned)A_R2) {
            transpose_tile_128(W2raw, w2t, HID, IN_DIM, blockIdx.x - A_R1, smem, tid);
            return;
        }
        if (blockIdx.x < (unsigned)A_R3) {
            int r = blockIdx.x - A_R2;
            int z = r / WT_W2, tI = r - z * WT_W2;
            transpose_tile_128(WoutRaw + (size_t)z * HID * IN_DIM,
                               woutt + (size_t)z * IN_DIM * HID,
                               HID, IN_DIM, tI, smem, tid);
            return;
        }
        // ---- gating block (128 threads) ----
        {
            const int n = blockIdx.x - A_R3;
            const int b = n / NCLS;
            const int t = n - b * NCLS;
            float* scls = reinterpret_cast<float*>(smem);
            float* slog = reinterpret_cast<float*>(smem + IN_DIM * 4);

            const float* crow = x + (size_t)(b * SEQ + t) * IN_DIM;
            for (int i = tid; i < IN_DIM; i += NTHREADS) scls[i] = crow[i];
            __syncthreads();

            for (int j = wid; j < 6; j += 4) {
                const float* wg = Wg + (size_t)t * IN_DIM * 6;
                float s = 0.0f;
                for (int d = lane; d < IN_DIM; d += 32)
                    s = fmaf(scls[d], wg[(size_t)d * 6 + j], s);
                #pragma unroll
                for (int off = 16; off > 0; off >>= 1)
                    s += __shfl_down_sync(0xffffffffu, s, off);
                if (lane == 0) slog[j] = s;
            }
            __syncthreads();

            if (tid == 0) {
                float l[6];
                #pragma unroll
                for (int j = 0; j < 6; j++) l[j] = slog[j];
                int i0 = 0;
                #pragma unroll
                for (int j = 1; j < 6; j++) if (l[j] > l[i0]) i0 = j;
                int i1 = (i0 == 0) ? 1 : 0;
                #pragma unroll
                for (int j = 0; j < 6; j++) if (j != i0 && l[j] > l[i1]) i1 = j;
                float p1 = expf(l[i1] - l[i0]);
                float inv = 1.0f / (1.0f + p1);
                float w0 = inv, w1 = p1 * inv;
                gI[n] = make_int2(i0, i1);
                gW[n] = make_float2(w0, w1);
                if (i0 > 0) {
                    int idx = atomicAdd(&cnt[i0 - 1], 1);
                    lst[(i0 - 1) * M_CLS + idx] = n;
                    wls[(i0 - 1) * M_CLS + idx] = w0;
                }
                if (i1 > 0) {
                    int idx = atomicAdd(&cnt[i1 - 1], 1);
                    lst[(i1 - 1) * M_CLS + idx] = n | (1 << 16);
                    wls[(i1 - 1) * M_CLS + idx] = w1;
                }
            }
            return;
        }
    }

    if (blockIdx.x < (unsigned)NBIG) {
        // ---------------- BIG PATH: 128x128 tile, 4 warps 2x2 ----------------
        const int wm = wid >> 1, wn = wid & 1;
        const int bi = blockIdx.x;
        const int NBX = (PHASE == 0) ? A_NBX : B_NBX;
        const int bm = (bi / NBX) * BM;
        const int bn = (bi % NBX) * BN;

        const __half* aG0 = A + (size_t)bm * K;
        const __half* bG0 = Bw + (size_t)bn * K;

        auto loadChunk = [&](int c) {
            const int slot = c % STAGES;
            const uint32_t aS = sb + (uint32_t)slot * (2 * STG_BYTES);
            const uint32_t bS = aS + STG_BYTES;
            const __half* aG = aG0 + c * BK;
            const __half* bG = bG0 + c * BK;
            #pragma unroll
            for (int t = 0; t < 8; t++) {
                int i = t * NTHREADS + tid;
                int row = i >> 3, g = i & 7;
                uint32_t off = (uint32_t)(row * 128 + g * 16);
                cp16(aS + sw128(off), aG + (size_t)row * K + g * 8);
            }
            #pragma unroll
            for (int t = 0; t < 8; t++) {
                int i = t * NTHREADS + tid;
                int row = i >> 3, g = i & 7;
                uint32_t off = (uint32_t)(row * 128 + g * 16);
                cp16(bS + sw128(off), bG + (size_t)row * K + g * 8);
            }
            CP_COMMIT();
        };

        float acc[4][8][4];
        #pragma unroll
        for (int i = 0; i < 4; i++)
            #pragma unroll
            for (int j = 0; j < 8; j++)
                #pragma unroll
                for (int q = 0; q < 4; q++) acc[i][j][q] = 0.0f;

        loadChunk(0);
        loadChunk(1);

        const int aRow = wm * 64 + (lane & 15);
        const int aCol = (lane >> 4) * 16;
        const int bRow = wn * 64 + ((lane >> 4) & 1) * 8 + (lane & 7);
        const int bCol = ((lane >> 3) & 1) * 16;

        for (int c = 0; c < C; c++) {
            if (c + 2 < C) { CP_WAIT(1); } else { CP_WAIT(0); }
            __syncthreads();
            if (c + 2 < C) loadChunk(c + 2);

            const int slot = c % STAGES;
            const uint32_t aS = sb + (uint32_t)slot * (2 * STG_BYTES);
            const uint32_t bS = aS + STG_BYTES;

            #pragma unroll
            for (int kk = 0; kk < 4; kk++) {
                uint32_t af[4][4];
                #pragma unroll
                for (int mt = 0; mt < 4; mt++) {
                    uint32_t off = (uint32_t)((aRow + mt * 16) * 128 + kk * 32 + aCol);
                    ldsm_x4(af[mt][0], af[mt][1], af[mt][2], af[mt][3], aS + sw128(off));
                }
                uint32_t bf[8][2];
                #pragma unroll
                for (int pr = 0; pr < 4; pr++) {
                    uint32_t off = (uint32_t)((bRow + pr * 16) * 128 + kk * 32 + bCol);
                    uint32_t r0, r1, r2, r3;
                    ldsm_x4(r0, r1, r2, r3, bS + sw128(off));
                    bf[pr * 2 + 0][0] = r0; bf[pr * 2 + 0][1] = r1;
                    bf[pr * 2 + 1][0] = r2; bf[pr * 2 + 1][1] = r3;
                }
                #pragma unroll
                for (int mt = 0; mt < 4; mt++)
                    #pragma unroll
                    for (int nt = 0; nt < 8; nt++)
                        mma_f16(acc[mt][nt][0], acc[mt][nt][1], acc[mt][nt][2], acc[mt][nt][3],
                                af[mt][0], af[mt][1], af[mt][2], af[mt][3],
                                bf[nt][0], bf[nt][1]);
            }
        }

        const int q = lane & 3;
        #pragma unroll
        for (int mt = 0; mt < 4; mt++) {
            #pragma unroll
            for (int h = 0; h < 2; h++) {
                const int rowg = bm + wm * 64 + mt * 16 + (lane >> 2) + h * 8;
                __half* rpH = nullptr;
                float*  rpF = nullptr;
                if (PHASE == 0) {
                    rpH = outH + (size_t)rowg * HID;
                } else {
                    if (rowg < M_PATCH) {
                        int bb = rowg / NUM_PATCH, p = rowg - bb * NUM_PATCH;
                        rpF = outF + (size_t)(bb * SEQ + NCLS + p) * IN_DIM;
                    } else {
                        rpF = outE0 + (size_t)(rowg - M_PATCH) * IN_DIM;
                    }
                }
                #pragma unroll
                for (int nt = 0; nt < 8; nt++) {
                    const int col = bn + wn * 64 + nt * 8 + q * 2;
                    float v0 = acc[mt][nt][h * 2 + 0] + bias[col];
                    float v1 = acc[mt][nt][h * 2 + 1] + bias[col + 1];
                    if (PHASE == 0) {
                        v0 = gelu_f(v0); v1 = gelu_f(v1);
                        __half2 hh; hh.x = __float2half(v0); hh.y = __float2half(v1);
                        *reinterpret_cast<__half2*>(rpH + col) = hh;
                    } else {
                        *reinterpret_cast<float2*>(rpF + col) = make_float2(v0, v1);
                    }
                }
            }
        }
    } else {
        // ---------------- GATHER PATH: 64x128 tile ----------------
        const int gbi = blockIdx.x - NBIG;
        const int wm = wid >> 1, wn = wid & 1;
        const int N = (PHASE == 0) ? HID : IN_DIM;

        int zsel, mtile, ntile;
        if (PHASE == 0) {
            const int nt = HID / GBN;
            int mslot = gbi / nt; ntile = gbi % nt;
            zsel  = (mslot <= 1) ? 0 : (mslot - 1);
            mtile = (mslot <= 1) ? mslot : 0;
        } else {
            zsel  = gbi / 36;
            int r = gbi % 36;
            mtile = r / 6; ntile = r % 6;
            if (mtile * GBM >= cnt[zsel]) return;
        }

        if (tid < GBM) {
            const __half* rp; int oi; float w = 1.0f;
            if (PHASE == 0) {
                int r = mtile * GBM + tid;
                int n = (zsel == 0) ? ((r < 64) ? r * 6 : (r - 64) * 6 + 5)
                                    : r * 6 + zsel;
                rp = Ag + (size_t)(M_PATCH + n) * IN_DIM;
                oi = n;
            } else {
                int r = mtile * GBM + tid;
                if (r < cnt[zsel]) {
                    int e = lst[zsel * M_CLS + r];
                    int n = e & 0xFFFF, s = e >> 16;
                    rp = Ag + (size_t)n * HID;
                    oi = n * 2 + s;
                    w  = wls[zsel * M_CLS + r];
                } else { rp = Ag; oi = -1; }
            }
            *reinterpret_cast<const __half**>(smem + tid * 8) = rp;
            reinterpret_cast<int*>(smem + 512)[tid]  = oi;
            reinterpret_cast<float*>(smem + 768)[tid] = w;
        }
        __syncthreads();

        const __half* bG0 = Wsm + (size_t)zsel * N * K + (size_t)(ntile * GBN) * K;
        const float* biasZ = biasSm + (size_t)zsel * N;

        auto loadChunkG = [&](int c) {
            const int slot = c % 3;
            const uint32_t aS = sb + 1024u + (uint32_t)slot * GSTG;
            const uint32_t bS = aS + GSTG_A;
            #pragma unroll
            for (int t = 0; t < 4; t++) {
                int i = t * 128 + tid;
                int row = i >> 3, g = i & 7;
                const __half* rp;
                asm("ld.shared.b64 %0, [%1];" : "=l"(rp) : "r"(sb + (uint32_t)(row * 8)));
                uint32_t off = (uint32_t)(row * 128 + g * 16);
                cp16(aS + sw128(off), rp + c * 64 + g * 8);
            }
            const __half* bG = bG0 + c * 64;
            #pragma unroll
            for (int t = 0; t < 8; t++) {
                int i = t * 128 + tid;
                int row = i >> 3, g = i & 7;
                uint32_t off = (uint32_t)(row * 128 + g * 16);
                cp16(bS + sw128(off), bG + (size_t)row * K + g * 8);
            }
            CP_COMMIT();
        };

        float acc[2][8][4];
        #pragma unroll
        for (int i = 0; i < 2; i++)
            #pragma unroll
            for (int j = 0; j < 8; j++)
                #pragma unroll
                for (int q = 0; q < 4; q++) acc[i][j][q] = 0.0f;

        loadChunkG(0);
        loadChunkG(1);

        const int aRow = wm * 32 + (lane & 15);
        const int aCol = (lane >> 4) * 16;
        const int bRow = wn * 64 + ((lane >> 4) & 1) * 8 + (lane & 7);
        const int bCol = ((lane >> 3) & 1) * 16;

        for (int c = 0; c < C; c++) {
            if (c + 2 < C) { CP_WAIT(1); } else { CP_WAIT(0); }
            __syncthreads();
            if (c + 2 < C) loadChunkG(c + 2);

            const int slot = c % 3;
            const uint32_t aS = sb + 1024u + (uint32_t)slot * GSTG;
            const uint32_t bS = aS + GSTG_A;

            #pragma unroll
            for (int kk = 0; kk < 4; kk++) {
                uint32_t af[2][4];
                #pragma unroll
                for (int mt = 0; mt < 2; mt++) {
                    uint32_t off = (uint32_t)((aRow + mt * 16) * 128 + kk * 32 + aCol);
                    ldsm_x4(af[mt][0], af[mt][1], af[mt][2], af[mt][3], aS + sw128(off));
                }
                uint32_t bf[8][2];
                #pragma unroll
                for (int pr = 0; pr < 4; pr++) {
                    uint32_t off = (uint32_t)((bRow + pr * 16) * 128 + kk * 32 + bCol);
                    uint32_t r0, r1, r2, r3;
                    ldsm_x4(r0, r1, r2, r3, bS + sw128(off));
                    bf[pr * 2 + 0][0] = r0; bf[pr * 2 + 0][1] = r1;
                    bf[pr * 2 + 1][0] = r2; bf[pr * 2 + 1][1] = r3;
                }
                #pragma unroll
                for (int mt = 0; mt < 2; mt++)
                    #pragma unroll
                    for (int nt = 0; nt < 8; nt++)
                        mma_f16(acc[mt][nt][0], acc[mt][nt][1], acc[mt][nt][2], acc[mt][nt][3],
                                af[mt][0], af[mt][1], af[mt][2], af[mt][3],
                                bf[nt][0], bf[nt][1]);
            }
        }

        const int q = lane & 3;
        #pragma unroll
        for (int mt = 0; mt < 2; mt++) {
            #pragma unroll
            for (int h = 0; h < 2; h++) {
                const int rowg = wm * 32 + mt * 16 + (lane >> 2) + h * 8;
                int   oi = reinterpret_cast<int*>(smem + 512)[rowg];
                float w  = reinterpret_cast<float*>(smem + 768)[rowg];
                #pragma unroll
                for (int nt = 0; nt < 8; nt++) {
                    const int col = ntile * GBN + wn * 64 + nt * 8 + q * 2;
                    float v0 = acc[mt][nt][h * 2 + 0] + biasZ[col];
                    float v1 = acc[mt][nt][h * 2 + 1] + biasZ[col + 1];
                    if (PHASE == 0) {
                        v0 = gelu_f(v0); v1 = gelu_f(v1);
                        __half2 hh; hh.x = __float2half(v0); hh.y = __float2half(v1);
                        *reinterpret_cast<__half2*>(outGH + (size_t)oi * HID + col) = hh;
                    } else if (oi >= 0) {
                        *reinterpret_cast<float2*>(outGF + (size_t)oi * IN_DIM + col)
                            = make_float2(w * v0, w * v1);
                    }
                }
            }
        }
    }
}

// ---------------- conversion kernel (phase-A prerequisites only) ----------------
#define CX_BLK   (M_ALL * IN_DIM / 8 / 256)            // 13968
#define CONV_TOTAL (CX_BLK + WT_W1 + WT_WIN)           // 27792

__global__ __launch_bounds__(256)
void conv_all(const float* __restrict__ x,   __half* __restrict__ xh,
              const float* __restrict__ W1,  __half* __restrict__ w1t,
              const float* __restrict__ Win, __half* __restrict__ wint)
{
    int bi = blockIdx.x;
    if (bi < CX_BLK) {
        int idx = bi * 256 + threadIdx.x;            // units of 8 elems
        int m  = idx / (IN_DIM / 8);
        int kp = (idx - m * (IN_DIM / 8)) * 8;
        int src;
        if (m < M_PATCH) { int b = m / NUM_PATCH, p = m - b * NUM_PATCH; src = b * SEQ + NCLS + p; }
        else             { int rr = m - M_PATCH; int b = rr / NCLS, t = rr - b * NCLS; src = b * SEQ + t; }
        const float* sp = x + (size_t)src * IN_DIM + kp;
        float4 v0 = *reinterpret_cast<const float4*>(sp);
        float4 v1 = *reinterpret_cast<const float4*>(sp + 4);
        __half2 h0; h0.x = __float2half(v0.x); h0.y = __float2half(v0.y);
        __half2 h1; h1.x = __float2half(v0.z); h1.y = __float2half(v0.w);
        __half2 h2; h2.x = __float2half(v1.x); h2.y = __float2half(v1.y);
        __half2 h3; h3.x = __float2half(v1.z); h3.y = __float2half(v1.w);
        uint4 pk;
        pk.x = *reinterpret_cast<uint32_t*>(&h0);
        pk.y = *reinterpret_cast<uint32_t*>(&h1);
        pk.z = *reinterpret_cast<uint32_t*>(&h2);
        pk.w = *reinterpret_cast<uint32_t*>(&h3);
        *reinterpret_cast<uint4*>(xh + (size_t)m * IN_DIM + kp) = pk;
        return;
    }
    bi -= CX_BLK;

    const float* W; __half* Wt; int tileIdx;
    if (bi < WT_W1) { W = W1; Wt = w1t; tileIdx = bi; }
    else {
        bi -= WT_W1;
        int z = bi / WT_W1; tileIdx = bi - z * WT_W1;
        W = Win + (size_t)z * IN_DIM * HID;
        Wt = wint + (size_t)z * HID * IN_DIM;
    }
    // K=IN_DIM, N=HID, 256-thread variant
    __shared__ float t[32][33];
    const int ktiles = IN_DIM / 32;
    int k0 = (tileIdx % ktiles) * 32, n0 = (tileIdx / ktiles) * 32;
    int tx = threadIdx.x & 31, ty = threadIdx.x >> 5;
    #pragma unroll
    for (int i = 0; i < 4; i++)
        t[ty + i * 8][tx] = W[(size_t)(k0 + ty + i * 8) * HID + n0 + tx];
    __syncthreads();
    #pragma unroll
    for (int it = 0; it < 2; it++) {
        int item = it * 256 + threadIdx.x;
        int n  = n0 + (item >> 4);
        int kp = (item & 15) * 2;
        __half2 hv;
        hv.x = __float2half(t[kp][item >> 4]);
        hv.y = __float2half(t[kp + 1][item >> 4]);
        *reinterpret_cast<__half2*>(Wt + (size_t)n * IN_DIM + k0 + kp) = hv;
    }
}

// ---------------- final mix (+ counter reset) ----------------
__global__ __launch_bounds__(192)
void final_mix(const float* __restrict__ e0,
               const float* __restrict__ moeOut,
               const int2* __restrict__ gI,
               const float2* __restrict__ gW,
               float* __restrict__ out,
               int* __restrict__ cnt)
{
    const int n = blockIdx.x;
    const int b = n / NCLS;
    const int t = n - b * NCLS;
    int2  ii = gI[n];
    float2 ww = gW[n];
    const float* e0row = e0 + (size_t)n * IN_DIM;
    const float* m0 = moeOut + (size_t)(n * 2 + 0) * IN_DIM;
    const float* m1 = moeOut + (size_t)(n * 2 + 1) * IN_DIM;
    float* orow = out + (size_t)(b * SEQ + t) * IN_DIM;
    for (int c = threadIdx.x; c < IN_DIM; c += 192) {
        float v = (ii.x == 0) ? ww.x * e0row[c] : m0[c];
        v      += (ii.y == 0) ? ww.y * e0row[c] : m1[c];
        orow[c] = v;
    }
    if (blockIdx.x == 0 && threadIdx.x < ATOMS) cnt[threadIdx.x] = 0;
}

// ---------------- launch ----------------
extern "C" void kernel_launch(void* const* d_in, const int* in_sizes, int n_in,
                              void* d_out, int out_size)
{
    const float* x     = (const float*)d_in[0];
    const float* W1    = (const float*)d_in[1];
    const float* b1    = (const float*)d_in[2];
    const float* W2    = (const float*)d_in[3];
    const float* b2    = (const float*)d_in[4];
    const float* W_in  = (const float*)d_in[5];
    const float* b_in  = (const float*)d_in[6];
    const float* W_out = (const float*)d_in[7];
    const float* b_out = (const float*)d_in[8];
    const float* Wg    = (const float*)d_in[9];
    float* out = (float*)d_out;

    static __half *xh = nullptr, *w1t, *hid, *w2t, *wint, *woutt, *hm2;
    static float *e0, *moeOut, *wls;
    static int *cnt, *lst;
    static int2 *gI;
    static float2 *gW;
    if (!xh) {
        cudaGetSymbolAddress((void**)&xh,    g_xh);
        cudaGetSymbolAddress((void**)&w1t,   g_w1t);
        cudaGetSymbolAddress((void**)&hid,   g_hid);
        cudaGetSymbolAddress((void**)&w2t,   g_w2t);
        cudaGetSymbolAddress((void**)&wint,  g_wint);
        cudaGetSymbolAddress((void**)&woutt, g_woutt);
        cudaGetSymbolAddress((void**)&hm2,   g_hm2);
        cudaGetSymbolAddress((void**)&e0,    g_e0);
        cudaGetSymbolAddress((void**)&moeOut,g_moeOut);
        cudaGetSymbolAddress((void**)&cnt,   g_cnt);
        cudaGetSymbolAddress((void**)&lst,   g_lst);
        cudaGetSymbolAddress((void**)&wls,   g_wls);
        cudaGetSymbolAddress((void**)&gI,    g_gI);
        cudaGetSymbolAddress((void**)&gW,    g_gW);
        cudaFuncSetAttribute((const void*)fused_gemm<0>,
                             cudaFuncAttributeMaxDynamicSharedMemorySize, SMEM_DYN);
        cudaFuncSetAttribute((const void*)fused_gemm<1>,
                             cudaFuncAttributeMaxDynamicSharedMemorySize, SMEM_DYN);
    }

    // 1: conversions needed by phase A (xh, w1t, wint)
    conv_all<<<CONV_TOTAL, 256>>>(x, xh, W1, w1t, W_in, wint);

    // 2: phase A big GEMM + hm2 gather + migrated W2/Wout transposes + gating
    fused_gemm<0><<<A_TOTAL, NTHREADS, SMEM_DYN>>>(
        xh, w1t, b1, hid, nullptr, nullptr,
        xh, wint, b_in, hm2, nullptr, cnt, lst, wls,
        W2, w2t, W_out, woutt, x, Wg, gI, gW);

    // 3: phase B big GEMM + moeOut gather tiles
    fused_gemm<1><<<B_TOTAL, NTHREADS, SMEM_DYN>>>(
        hid, w2t, b2, nullptr, out, e0,
        hm2, woutt, b_out, nullptr, moeOut, cnt, lst, wls,
        nullptr, nullptr, nullptr, nullptr, nullptr, nullptr, nullptr, nullptr);

    // 4: final mix + counter reset
    final_mix<<<M_CLS, 192>>>(e0, moeOut, gI, gW, out, cnt);
}

// round 16
// speedup vs baseline: 1.0342x; 1.0342x over previous
#include <cuda_runtime.h>
#include <cuda_fp16.h>
#include <math.h>
#include <stdint.h>

// ---------------- problem constants ----------------
#define IN_DIM   768
#define HID      3072
#define BATCH    64
#define NCLS     6
#define NUM_PATCH 576
#define ATOMS    5
#define SEQ      (NCLS + NUM_PATCH)          // 582
#define M_PATCH  (BATCH * NUM_PATCH)         // 36864
#define M_CLS    (BATCH * NCLS)              // 384
#define M_ALL    (M_PATCH + M_CLS)           // 37248

// ---------------- device scratch ----------------
__device__ __half g_xh  [(size_t)M_ALL * IN_DIM];
__device__ __half g_w1t [(size_t)HID * IN_DIM];
__device__ __half g_hid [(size_t)M_ALL * HID];
__device__ __half g_w2t [(size_t)IN_DIM * HID];
__device__ __half g_wint [(size_t)ATOMS * HID * IN_DIM];
__device__ __half g_woutt[(size_t)ATOMS * IN_DIM * HID];
__device__ __half g_hm2 [(size_t)M_CLS * HID];
__device__ float g_e0  [(size_t)M_CLS * IN_DIM];
__device__ float g_moeOut[(size_t)M_CLS * 2 * IN_DIM];
__device__ int   g_cnt [ATOMS];                  // zero-init at load; final_mix re-zeroes
__device__ int   g_lst [ATOMS * M_CLS];
__device__ float g_wls [ATOMS * M_CLS];
__device__ int2  g_gI  [M_CLS];
__device__ float2 g_gW [M_CLS];

__device__ __forceinline__ float gelu_f(float v) {
    return 0.5f * v * (1.0f + erff(v * 0.7071067811865476f));
}

// ---------------- PTX helpers ----------------
__device__ __forceinline__ uint32_t smem_u32(const void* p) {
    uint32_t a;
    asm("{ .reg .u64 t; cvta.to.shared.u64 t, %1; cvt.u32.u64 %0, t; }" : "=r"(a) : "l"(p));
    return a;
}
__device__ __forceinline__ void cp16(uint32_t d, const void* s) {
    asm volatile("cp.async.cg.shared.global [%0], [%1], 16;" :: "r"(d), "l"(s));
}
#define CP_COMMIT()  asm volatile("cp.async.commit_group;" ::: "memory")
#define CP_WAIT(n)   asm volatile("cp.async.wait_group %0;" :: "n"(n) : "memory")

__device__ __forceinline__ void ldsm_x4(uint32_t& r0, uint32_t& r1, uint32_t& r2, uint32_t& r3,
                                        uint32_t addr) {
    asm volatile("ldmatrix.sync.aligned.m8n8.x4.shared.b16 {%0,%1,%2,%3}, [%4];"
                 : "=r"(r0), "=r"(r1), "=r"(r2), "=r"(r3) : "r"(addr));
}
__device__ __forceinline__ void mma_f16(float& c0, float& c1, float& c2, float& c3,
                                        uint32_t a0, uint32_t a1, uint32_t a2, uint32_t a3,
                                        uint32_t b0, uint32_t b1) {
    asm volatile("mma.sync.aligned.m16n8k16.row.col.f32.f16.f16.f32 "
                 "{%0,%1,%2,%3}, {%4,%5,%6,%7}, {%8,%9}, {%0,%1,%2,%3};"
                 : "+f"(c0), "+f"(c1), "+f"(c2), "+f"(c3)
                 : "r"(a0), "r"(a1), "r"(a2), "r"(a3), "r"(b0), "r"(b1));
}
__device__ __forceinline__ uint32_t sw128(uint32_t off) {
    return off ^ ((off >> 3) & 0x70);
}

// ---------------- fused GEMM (big path + gathered MoE path in one grid) ----------------
#define BM 128
#define BN 128
#define BK 64
#define STAGES 3
#define STG_BYTES (BM * 128)
#define SMEM_DYN (STAGES * 2 * STG_BYTES)        // 96 KB
#define NTHREADS 128

#define A_NBX    (HID / BN)                      // 24
#define A_NBIG   (A_NBX * (M_ALL / BM))          // 6984
#define B_NBX    (IN_DIM / BN)                   // 6
#define B_NBIG   (B_NBX * (M_ALL / BM))          // 1746

#define GBM 64
#define GBN 128
#define GSTG_A (GBM * 128)                       // 8 KB
#define GSTG_B (GBN * 128)                       // 16 KB
#define GSTG (GSTG_A + GSTG_B)                   // 24 KB
#define HM_BLOCKS  (6 * (HID / GBN))             // 144
#define MOE_BLOCKS (ATOMS * 6 * (IN_DIM / GBN))  // 180
#define A_TOTAL (A_NBIG + HM_BLOCKS)             // 7128
#define B_TOTAL (B_NBIG + MOE_BLOCKS)            // 1926

template<int PHASE>
__global__ __launch_bounds__(NTHREADS, 2)
void fused_gemm(const __half* __restrict__ A,
                const __half* __restrict__ Bw,
                const float* __restrict__ bias,
                __half* __restrict__ outH,
                float* __restrict__ outF,
                float* __restrict__ outE0,
                const __half* __restrict__ Ag,
                const __half* __restrict__ Wsm,
                const float* __restrict__ biasSm,
                __half* __restrict__ outGH,
                float* __restrict__ outGF,
                const int* __restrict__ cnt,
                const int* __restrict__ lst,
                const float* __restrict__ wls)
{
    extern __shared__ char smem[];
    const uint32_t sb = smem_u32(smem);
    const int tid  = threadIdx.x;
    const int wid  = tid >> 5, lane = tid & 31;
    const int NBIG = (PHASE == 0) ? A_NBIG : B_NBIG;
    const int K    = (PHASE == 0) ? IN_DIM : HID;
    const int C    = K >> 6;

    if (blockIdx.x < (unsigned)NBIG) {
        // ---------------- BIG PATH: 128x128 tile, 4 warps 2x2 ----------------
        const int wm = wid >> 1, wn = wid & 1;
        const int bi = blockIdx.x;
        const int NBX = (PHASE == 0) ? A_NBX : B_NBX;
        const int bm = (bi / NBX) * BM;
        const int bn = (bi % NBX) * BN;

        const __half* aG0 = A + (size_t)bm * K;
        const __half* bG0 = Bw + (size_t)bn * K;

        auto loadChunk = [&](int c) {
            const int slot = c % STAGES;
            const uint32_t aS = sb + (uint32_t)slot * (2 * STG_BYTES);
            const uint32_t bS = aS + STG_BYTES;
            const __half* aG = aG0 + c * BK;
            const __half* bG = bG0 + c * BK;
            #pragma unroll
            for (int t = 0; t < 8; t++) {
                int i = t * NTHREADS + tid;
                int row = i >> 3, g = i & 7;
                uint32_t off = (uint32_t)(row * 128 + g * 16);
                cp16(aS + sw128(off), aG + (size_t)row * K + g * 8);
            }
            #pragma unroll
            for (int t = 0; t < 8; t++) {
                int i = t * NTHREADS + tid;
                int row = i >> 3, g = i & 7;
                uint32_t off = (uint32_t)(row * 128 + g * 16);
                cp16(bS + sw128(off), bG + (size_t)row * K + g * 8);
            }
            CP_COMMIT();
        };

        float acc[4][8][4];
        #pragma unroll
        for (int i = 0; i < 4; i++)
            #pragma unroll
            for (int j = 0; j < 8; j++)
                #pragma unroll
                for (int q = 0; q < 4; q++) acc[i][j][q] = 0.0f;

        loadChunk(0);
        loadChunk(1);

        const int aRow = wm * 64 + (lane & 15);
        const int aCol = (lane >> 4) * 16;
        const int bRow = wn * 64 + ((lane >> 4) & 1) * 8 + (lane & 7);
        const int bCol = ((lane >> 3) & 1) * 16;

        for (int c = 0; c < C; c++) {
            if (c + 2 < C) { CP_WAIT(1); } else { CP_WAIT(0); }
            __syncthreads();
            if (c + 2 < C) loadChunk(c + 2);

            const int slot = c % STAGES;
            const uint32_t aS = sb + (uint32_t)slot * (2 * STG_BYTES);
            const uint32_t bS = aS + STG_BYTES;

            #pragma unroll
            for (int kk = 0; kk < 4; kk++) {
                uint32_t af[4][4];
                #pragma unroll
                for (int mt = 0; mt < 4; mt++) {
                    uint32_t off = (uint32_t)((aRow + mt * 16) * 128 + kk * 32 + aCol);
                    ldsm_x4(af[mt][0], af[mt][1], af[mt][2], af[mt][3], aS + sw128(off));
                }
                uint32_t bf[8][2];
                #pragma unroll
                for (int pr = 0; pr < 4; pr++) {
                    uint32_t off = (uint32_t)((bRow + pr * 16) * 128 + kk * 32 + bCol);
                    uint32_t r0, r1, r2, r3;
                    ldsm_x4(r0, r1, r2, r3, bS + sw128(off));
                    bf[pr * 2 + 0][0] = r0; bf[pr * 2 + 0][1] = r1;
                    bf[pr * 2 + 1][0] = r2; bf[pr * 2 + 1][1] = r3;
                }
                #pragma unroll
                for (int mt = 0; mt < 4; mt++)
                    #pragma unroll
                    for (int nt = 0; nt < 8; nt++)
                        mma_f16(acc[mt][nt][0], acc[mt][nt][1], acc[mt][nt][2], acc[mt][nt][3],
                                af[mt][0], af[mt][1], af[mt][2], af[mt][3],
                                bf[nt][0], bf[nt][1]);
            }
        }

        const int q = lane & 3;
        #pragma unroll
        for (int mt = 0; mt < 4; mt++) {
            #pragma unroll
            for (int h = 0; h < 2; h++) {
                const int rowg = bm + wm * 64 + mt * 16 + (lane >> 2) + h * 8;
                __half* rpH = nullptr;
                float*  rpF = nullptr;
                if (PHASE == 0) {
                    rpH = outH + (size_t)rowg * HID;
                } else {
                    if (rowg < M_PATCH) {
                        int bb = rowg / NUM_PATCH, p = rowg - bb * NUM_PATCH;
                        rpF = outF + (size_t)(bb * SEQ + NCLS + p) * IN_DIM;
                    } else {
                        rpF = outE0 + (size_t)(rowg - M_PATCH) * IN_DIM;
                    }
                }
                #pragma unroll
                for (int nt = 0; nt < 8; nt++) {
                    const int col = bn + wn * 64 + nt * 8 + q * 2;
                    float v0 = acc[mt][nt][h * 2 + 0] + bias[col];
                    float v1 = acc[mt][nt][h * 2 + 1] + bias[col + 1];
                    if (PHASE == 0) {
                        v0 = gelu_f(v0); v1 = gelu_f(v1);
                        __half2 hh; hh.x = __float2half(v0); hh.y = __float2half(v1);
                        *reinterpret_cast<__half2*>(rpH + col) = hh;
                    } else {
                        *reinterpret_cast<float2*>(rpF + col) = make_float2(v0, v1);
                    }
                }
            }
        }
    } else {
        // ---------------- GATHER PATH: 64x128 tile ----------------
        const int gbi = blockIdx.x - NBIG;
        const int wm = wid >> 1, wn = wid & 1;
        const int N = (PHASE == 0) ? HID : IN_DIM;

        int zsel, mtile, ntile;
        if (PHASE == 0) {
            const int nt = HID / GBN;
            int mslot = gbi / nt; ntile = gbi % nt;
            zsel  = (mslot <= 1) ? 0 : (mslot - 1);
            mtile = (mslot <= 1) ? mslot : 0;
        } else {
            zsel  = gbi / 36;
            int r = gbi % 36;
            mtile = r / 6; ntile = r % 6;
            if (mtile * GBM >= cnt[zsel]) return;
        }

        if (tid < GBM) {
            const __half* rp; int oi; float w = 1.0f;
            if (PHASE == 0) {
                int r = mtile * GBM + tid;
                int n = (zsel == 0) ? ((r < 64) ? r * 6 : (r - 64) * 6 + 5)
                                    : r * 6 + zsel;
                rp = Ag + (size_t)(M_PATCH + n) * IN_DIM;
                oi = n;
            } else {
                int r = mtile * GBM + tid;
                if (r < cnt[zsel]) {
                    int e = lst[zsel * M_CLS + r];
                    int n = e & 0xFFFF, s = e >> 16;
                    rp = Ag + (size_t)n * HID;
                    oi = n * 2 + s;
                    w  = wls[zsel * M_CLS + r];
                } else { rp = Ag; oi = -1; }
            }
            *reinterpret_cast<const __half**>(smem + tid * 8) = rp;
            reinterpret_cast<int*>(smem + 512)[tid]  = oi;
            reinterpret_cast<float*>(smem + 768)[tid] = w;
        }
        __syncthreads();

        const __half* bG0 = Wsm + (size_t)zsel * N * K + (size_t)(ntile * GBN) * K;
        const float* biasZ = biasSm + (size_t)zsel * N;

        auto loadChunkG = [&](int c) {
            const int slot = c % 3;
            const uint32_t aS = sb + 1024u + (uint32_t)slot * GSTG;
            const uint32_t bS = aS + GSTG_A;
            #pragma unroll
            for (int t = 0; t < 4; t++) {
                int i = t * 128 + tid;
                int row = i >> 3, g = i & 7;
                const __half* rp;
                asm("ld.shared.b64 %0, [%1];" : "=l"(rp) : "r"(sb + (uint32_t)(row * 8)));
                uint32_t off = (uint32_t)(row * 128 + g * 16);
                cp16(aS + sw128(off), rp + c * 64 + g * 8);
            }
            const __half* bG = bG0 + c * 64;
            #pragma unroll
            for (int t = 0; t < 8; t++) {
                int i = t * 128 + tid;
                int row = i >> 3, g = i & 7;
                uint32_t off = (uint32_t)(row * 128 + g * 16);
                cp16(bS + sw128(off), bG + (size_t)row * K + g * 8);
            }
            CP_COMMIT();
        };

        float acc[2][8][4];
        #pragma unroll
        for (int i = 0; i < 2; i++)
            #pragma unroll
            for (int j = 0; j < 8; j++)
                #pragma unroll
                for (int q = 0; q < 4; q++) acc[i][j][q] = 0.0f;

        loadChunkG(0);
        loadChunkG(1);

        const int aRow = wm * 32 + (lane & 15);
        const int aCol = (lane >> 4) * 16;
        const int bRow = wn * 64 + ((lane >> 4) & 1) * 8 + (lane & 7);
        const int bCol = ((lane >> 3) & 1) * 16;

        for (int c = 0; c < C; c++) {
            if (c + 2 < C) { CP_WAIT(1); } else { CP_WAIT(0); }
            __syncthreads();
            if (c + 2 < C) loadChunkG(c + 2);

            const int slot = c % 3;
            const uint32_t aS = sb + 1024u + (uint32_t)slot * GSTG;
            const uint32_t bS = aS + GSTG_A;

            #pragma unroll
            for (int kk = 0; kk < 4; kk++) {
                uint32_t af[2][4];
                #pragma unroll
                for (int mt = 0; mt < 2; mt++) {
                    uint32_t off = (uint32_t)((aRow + mt * 16) * 128 + kk * 32 + aCol);
                    ldsm_x4(af[mt][0], af[mt][1], af[mt][2], af[mt][3], aS + sw128(off));
                }
                uint32_t bf[8][2];
                #pragma unroll
                for (int pr = 0; pr < 4; pr++) {
                    uint32_t off = (uint32_t)((bRow + pr * 16) * 128 + kk * 32 + bCol);
                    uint32_t r0, r1, r2, r3;
                    ldsm_x4(r0, r1, r2, r3, bS + sw128(off));
                    bf[pr * 2 + 0][0] = r0; bf[pr * 2 + 0][1] = r1;
                    bf[pr * 2 + 1][0] = r2; bf[pr * 2 + 1][1] = r3;
                }
                #pragma unroll
                for (int mt = 0; mt < 2; mt++)
                    #pragma unroll
                    for (int nt = 0; nt < 8; nt++)
                        mma_f16(acc[mt][nt][0], acc[mt][nt][1], acc[mt][nt][2], acc[mt][nt][3],
                                af[mt][0], af[mt][1], af[mt][2], af[mt][3],
                                bf[nt][0], bf[nt][1]);
            }
        }

        const int q = lane & 3;
        #pragma unroll
        for (int mt = 0; mt < 2; mt++) {
            #pragma unroll
            for (int h = 0; h < 2; h++) {
                const int rowg = wm * 32 + mt * 16 + (lane >> 2) + h * 8;
                int   oi = reinterpret_cast<int*>(smem + 512)[rowg];
                float w  = reinterpret_cast<float*>(smem + 768)[rowg];
                #pragma unroll
                for (int nt = 0; nt < 8; nt++) {
                    const int col = ntile * GBN + wn * 64 + nt * 8 + q * 2;
                    float v0 = acc[mt][nt][h * 2 + 0] + biasZ[col];
                    float v1 = acc[mt][nt][h * 2 + 1] + biasZ[col + 1];
                    if (PHASE == 0) {
                        v0 = gelu_f(v0); v1 = gelu_f(v1);
                        __half2 hh; hh.x = __float2half(v0); hh.y = __float2half(v1);
                        *reinterpret_cast<__half2*>(outGH + (size_t)oi * HID + col) = hh;
                    } else if (oi >= 0) {
                        *reinterpret_cast<float2*>(outGF + (size_t)oi * IN_DIM + col)
                            = make_float2(w * v0, w * v1);
                    }
                }
            }
        }
    }
}

// ---------------- fused conversion + gating kernel (R14 layout) ----------------
#define CX_BLK   (M_ALL * IN_DIM / 8 / 256)            // 13968 (8 elems/thread)
#define WT_W1    (IN_DIM / 32 * (HID / 32))
#define WT_W2    (HID / 32 * (IN_DIM / 32))
#define WT_WIN   (WT_W1 * ATOMS)
#define WT_WOUT  (WT_W2 * ATOMS)
#define CONV_BLOCKS (CX_BLK + WT_W1 + WT_W2 + WT_WIN + WT_WOUT)
#define CONV_TOTAL (CONV_BLOCKS + M_CLS)

__global__ __launch_bounds__(256)
void conv_all(const float* __restrict__ x,   __half* __restrict__ xh,
              const float* __restrict__ W1,  __half* __restrict__ w1t,
              const float* __restrict__ W2,  __half* __restrict__ w2t,
              const float* __restrict__ Win, __half* __restrict__ wint,
              const float* __restrict__ Wout,__half* __restrict__ woutt,
              const float* __restrict__ Wg,
              int* __restrict__ cnt, int* __restrict__ lst, float* __restrict__ wls,
              int2* __restrict__ gI, float2* __restrict__ gW)
{
    int bi = blockIdx.x;
    if (bi < CX_BLK) {
        int idx = bi * 256 + threadIdx.x;            // units of 8 elems
        int m  = idx / (IN_DIM / 8);
        int kp = (idx - m * (IN_DIM / 8)) * 8;
        int src;
        if (m < M_PATCH) { int b = m / NUM_PATCH, p = m - b * NUM_PATCH; src = b * SEQ + NCLS + p; }
        else             { int rr = m - M_PATCH; int b = rr / NCLS, t = rr - b * NCLS; src = b * SEQ + t; }
        const float* sp = x + (size_t)src * IN_DIM + kp;
        float4 v0 = *reinterpret_cast<const float4*>(sp);
        float4 v1 = *reinterpret_cast<const float4*>(sp + 4);
        __half2 h0; h0.x = __float2half(v0.x); h0.y = __float2half(v0.y);
        __half2 h1; h1.x = __float2half(v0.z); h1.y = __float2half(v0.w);
        __half2 h2; h2.x = __float2half(v1.x); h2.y = __float2half(v1.y);
        __half2 h3; h3.x = __float2half(v1.z); h3.y = __float2half(v1.w);
        uint4 pk;
        pk.x = *reinterpret_cast<uint32_t*>(&h0);
        pk.y = *reinterpret_cast<uint32_t*>(&h1);
        pk.z = *reinterpret_cast<uint32_t*>(&h2);
        pk.w = *reinterpret_cast<uint32_t*>(&h3);
        *reinterpret_cast<uint4*>(xh + (size_t)m * IN_DIM + kp) = pk;
        return;
    }
    bi -= CX_BLK;

    if (bi >= WT_W1 + WT_W2 + WT_WIN + WT_WOUT) {
        // ---- gating block: one per cls token ----
        const int n = bi - (WT_W1 + WT_W2 + WT_WIN + WT_WOUT);
        const int b = n / NCLS;
        const int t = n - b * NCLS;

        __shared__ float scls[IN_DIM];
        __shared__ float slog[6];

        const float* crow = x + (size_t)(b * SEQ + t) * IN_DIM;
        for (int i = threadIdx.x; i < IN_DIM; i += 256) scls[i] = crow[i];
        __syncthreads();

        const int w = threadIdx.x >> 5, lane = threadIdx.x & 31;
        if (w < 6) {
            const float* wg = Wg + (size_t)t * IN_DIM * 6;
            float s = 0.0f;
            for (int d = lane; d < IN_DIM; d += 32)
                s = fmaf(scls[d], wg[(size_t)d * 6 + w], s);
            #pragma unroll
            for (int off = 16; off > 0; off >>= 1)
                s += __shfl_down_sync(0xffffffffu, s, off);
            if (lane == 0) slog[w] = s;
        }
        __syncthreads();

        if (threadIdx.x == 0) {
            float l[6];
            #pragma unroll
            for (int j = 0; j < 6; j++) l[j] = slog[j];
            int i0 = 0;
            #pragma unroll
            for (int j = 1; j < 6; j++) if (l[j] > l[i0]) i0 = j;
            int i1 = (i0 == 0) ? 1 : 0;
            #pragma unroll
            for (int j = 0; j < 6; j++) if (j != i0 && l[j] > l[i1]) i1 = j;
            float p1 = expf(l[i1] - l[i0]);
            float inv = 1.0f / (1.0f + p1);
            float w0 = inv, w1 = p1 * inv;
            gI[n] = make_int2(i0, i1);
            gW[n] = make_float2(w0, w1);
            if (i0 > 0) {
                int idx = atomicAdd(&cnt[i0 - 1], 1);
                lst[(i0 - 1) * M_CLS + idx] = n;
                wls[(i0 - 1) * M_CLS + idx] = w0;
            }
            if (i1 > 0) {
                int idx = atomicAdd(&cnt[i1 - 1], 1);
                lst[(i1 - 1) * M_CLS + idx] = n | (1 << 16);
                wls[(i1 - 1) * M_CLS + idx] = w1;
            }
        }
        return;
    }

    const float* W; __half* Wt; int K, N, tileIdx;
    if (bi < WT_W1)                   { W = W1;  Wt = w1t;  K = IN_DIM; N = HID;    tileIdx = bi; }
    else if ((bi -= WT_W1)  < WT_W2)  { W = W2;  Wt = w2t;  K = HID;    N = IN_DIM; tileIdx = bi; }
    else if ((bi -= WT_W2)  < WT_WIN) {
        int z = bi / WT_W1; tileIdx = bi - z * WT_W1;
        W = Win  + (size_t)z * IN_DIM * HID; Wt = wint  + (size_t)z * HID * IN_DIM;
        K = IN_DIM; N = HID;
    } else {
        bi -= WT_WIN;
        int z = bi / WT_W2; tileIdx = bi - z * WT_W2;
        W = Wout + (size_t)z * HID * IN_DIM; Wt = woutt + (size_t)z * IN_DIM * HID;
        K = HID; N = IN_DIM;
    }

    __shared__ float t[32][33];
    const int ktiles = K / 32;
    int k0 = (tileIdx % ktiles) * 32, n0 = (tileIdx / ktiles) * 32;
    int tx = threadIdx.x & 31, ty = threadIdx.x >> 5;
    #pragma unroll
    for (int i = 0; i < 4; i++)
        t[ty + i * 8][tx] = W[(size_t)(k0 + ty + i * 8) * N + n0 + tx];
    __syncthreads();
    #pragma unroll
    for (int it = 0; it < 2; it++) {
        int item = it * 256 + threadIdx.x;
        int n  = n0 + (item >> 4);
        int kp = (item & 15) * 2;
        __half2 hv;
        hv.x = __float2half(t[kp][item >> 4]);
        hv.y = __float2half(t[kp + 1][item >> 4]);
        *reinterpret_cast<__half2*>(Wt + (size_t)n * K + k0 + kp) = hv;
    }
}

// ---------------- final mix (float4, 256 threads, + counter reset) ----------------
__global__ __launch_bounds__(256)
void final_mix(const float* __restrict__ e0,
               const float* __restrict__ moeOut,
               const int2* __restrict__ gI,
               const float2* __restrict__ gW,
               float* __restrict__ out,
               int* __restrict__ cnt)
{
    const int n = blockIdx.x;
    const int b = n / NCLS;
    const int t = n - b * NCLS;
    int2  ii = gI[n];
    float2 ww = gW[n];
    const float* e0row = e0 + (size_t)n * IN_DIM;
    const float* m0 = moeOut + (size_t)(n * 2 + 0) * IN_DIM;
    const float* m1 = moeOut + (size_t)(n * 2 + 1) * IN_DIM;
    float* orow = out + (size_t)(b * SEQ + t) * IN_DIM;
    // 192 float4 items, 256 threads -> single pass with bound check
    int c4 = threadIdx.x;
    if (c4 < IN_DIM / 4) {
        int c = c4 * 4;
        float4 e = *reinterpret_cast<const float4*>(e0row + c);
        float4 a = *reinterpret_cast<const float4*>(m0 + c);
        float4 bvec = *reinterpret_cast<const float4*>(m1 + c);
        float4 r;
        r.x = ((ii.x == 0) ? ww.x * e.x : a.x) + ((ii.y == 0) ? ww.y * e.x : bvec.x);
        r.y = ((ii.x == 0) ? ww.x * e.y : a.y) + ((ii.y == 0) ? ww.y * e.y : bvec.y);
        r.z = ((ii.x == 0) ? ww.x * e.z : a.z) + ((ii.y == 0) ? ww.y * e.z : bvec.z);
        r.w = ((ii.x == 0) ? ww.x * e.w : a.w) + ((ii.y == 0) ? ww.y * e.w : bvec.w);
        *reinterpret_cast<float4*>(orow + c) = r;
    }
    if (blockIdx.x == 0 && threadIdx.x >= 224 && threadIdx.x < 224 + ATOMS)
        cnt[threadIdx.x - 224] = 0;
}

// ---------------- launch ----------------
extern "C" void kernel_launch(void* const* d_in, const int* in_sizes, int n_in,
                              void* d_out, int out_size)
{
    const float* x     = (const float*)d_in[0];
    const float* W1    = (const float*)d_in[1];
    const float* b1    = (const float*)d_in[2];
    const float* W2    = (const float*)d_in[3];
    const float* b2    = (const float*)d_in[4];
    const float* W_in  = (const float*)d_in[5];
    const float* b_in  = (const float*)d_in[6];
    const float* W_out = (const float*)d_in[7];
    const float* b_out = (const float*)d_in[8];
    const float* Wg    = (const float*)d_in[9];
    float* out = (float*)d_out;

    static __half *xh = nullptr, *w1t, *hid, *w2t, *wint, *woutt, *hm2;
    static float *e0, *moeOut, *wls;
    static int *cnt, *lst;
    static int2 *gI;
    static float2 *gW;
    if (!xh) {
        cudaGetSymbolAddress((void**)&xh,    g_xh);
        cudaGetSymbolAddress((void**)&w1t,   g_w1t);
        cudaGetSymbolAddress((void**)&hid,   g_hid);
        cudaGetSymbolAddress((void**)&w2t,   g_w2t);
        cudaGetSymbolAddress((void**)&wint,  g_wint);
        cudaGetSymbolAddress((void**)&woutt, g_woutt);
        cudaGetSymbolAddress((void**)&hm2,   g_hm2);
        cudaGetSymbolAddress((void**)&e0,    g_e0);
        cudaGetSymbolAddress((void**)&moeOut,g_moeOut);
        cudaGetSymbolAddress((void**)&cnt,   g_cnt);
        cudaGetSymbolAddress((void**)&lst,   g_lst);
        cudaGetSymbolAddress((void**)&wls,   g_wls);
        cudaGetSymbolAddress((void**)&gI,    g_gI);
        cudaGetSymbolAddress((void**)&gW,    g_gW);
        cudaFuncSetAttribute((const void*)fused_gemm<0>,
                             cudaFuncAttributeMaxDynamicSharedMemorySize, SMEM_DYN);
        cudaFuncSetAttribute((const void*)fused_gemm<1>,
                             cudaFuncAttributeMaxDynamicSharedMemorySize, SMEM_DYN);
    }

    // 1: conversions + gating fused (cnt is 0 on entry)
    conv_all<<<CONV_TOTAL, 256>>>(x, xh, W1, w1t, W2, w2t, W_in, wint, W_out, woutt,
                                  Wg, cnt, lst, wls, gI, gW);

    // 2: phase A big GEMM + hm2 gather tiles
    fused_gemm<0><<<A_TOTAL, NTHREADS, SMEM_DYN>>>(
        xh, w1t, b1, hid, nullptr, nullptr,
        xh, wint, b_in, hm2, nullptr, cnt, lst, wls);

    // 3: phase B big GEMM + moeOut gather tiles
    fused_gemm<1><<<B_TOTAL, NTHREADS, SMEM_DYN>>>(
        hid, w2t, b2, nullptr, out, e0,
        hm2, woutt, b_out, nullptr, moeOut, cnt, lst, wls);

    // 4: final mix + counter reset
    final_mix<<<M_CLS, 256>>>(e0, moeOut, gI, gW, out, cnt);
}

// round 17
// speedup vs baseline: 1.0358x; 1.0016x over previous
#include <cuda_runtime.h>
#include <cuda_fp16.h>
#include <math.h>
#include <stdint.h>

// ---------------- problem constants ----------------
#define IN_DIM   768
#define HID      3072
#define BATCH    64
#define NCLS     6
#define NUM_PATCH 576
#define ATOMS    5
#define SEQ      (NCLS + NUM_PATCH)          // 582
#define M_PATCH  (BATCH * NUM_PATCH)         // 36864
#define M_CLS    (BATCH * NCLS)              // 384
#define M_ALL    (M_PATCH + M_CLS)           // 37248

// ---------------- device scratch ----------------
__device__ __half g_xh  [(size_t)M_ALL * IN_DIM];
__device__ __half g_w1t [(size_t)HID * IN_DIM];
__device__ __half g_hid [(size_t)M_ALL * HID];
__device__ __half g_w2t [(size_t)IN_DIM * HID];
__device__ __half g_wint [(size_t)ATOMS * HID * IN_DIM];
__device__ __half g_woutt[(size_t)ATOMS * IN_DIM * HID];
__device__ __half g_hm2 [(size_t)M_CLS * HID];
__device__ int   g_cnt [ATOMS];                  // zero-init at load; ticket re-zeroes
__device__ int   g_done = 0;                     // phase-B gather completion ticket
__device__ int   g_lst [ATOMS * M_CLS];
__device__ float g_wls [ATOMS * M_CLS];
__device__ float g_wE0 [M_CLS];                  // per-token weight on the e0 expert

__device__ __forceinline__ float gelu_f(float v) {
    return 0.5f * v * (1.0f + erff(v * 0.7071067811865476f));
}

// ---------------- PTX helpers ----------------
__device__ __forceinline__ uint32_t smem_u32(const void* p) {
    uint32_t a;
    asm("{ .reg .u64 t; cvta.to.shared.u64 t, %1; cvt.u32.u64 %0, t; }" : "=r"(a) : "l"(p));
    return a;
}
__device__ __forceinline__ void cp16(uint32_t d, const void* s) {
    asm volatile("cp.async.cg.shared.global [%0], [%1], 16;" :: "r"(d), "l"(s));
}
#define CP_COMMIT()  asm volatile("cp.async.commit_group;" ::: "memory")
#define CP_WAIT(n)   asm volatile("cp.async.wait_group %0;" :: "n"(n) : "memory")

__device__ __forceinline__ void ldsm_x4(uint32_t& r0, uint32_t& r1, uint32_t& r2, uint32_t& r3,
                                        uint32_t addr) {
    asm volatile("ldmatrix.sync.aligned.m8n8.x4.shared.b16 {%0,%1,%2,%3}, [%4];"
                 : "=r"(r0), "=r"(r1), "=r"(r2), "=r"(r3) : "r"(addr));
}
__device__ __forceinline__ void mma_f16(float& c0, float& c1, float& c2, float& c3,
                                        uint32_t a0, uint32_t a1, uint32_t a2, uint32_t a3,
                                        uint32_t b0, uint32_t b1) {
    asm volatile("mma.sync.aligned.m16n8k16.row.col.f32.f16.f16.f32 "
                 "{%0,%1,%2,%3}, {%4,%5,%6,%7}, {%8,%9}, {%0,%1,%2,%3};"
                 : "+f"(c0), "+f"(c1), "+f"(c2), "+f"(c3)
                 : "r"(a0), "r"(a1), "r"(a2), "r"(a3), "r"(b0), "r"(b1));
}
__device__ __forceinline__ uint32_t sw128(uint32_t off) {
    return off ^ ((off >> 3) & 0x70);
}

// ---------------- fused GEMM (big path + gathered MoE path in one grid) ----------------
#define BM 128
#define BN 128
#define BK 64
#define STAGES 3
#define STG_BYTES (BM * 128)
#define SMEM_DYN (STAGES * 2 * STG_BYTES)        // 96 KB
#define NTHREADS 128

#define A_NBX    (HID / BN)                      // 24
#define A_NBIG   (A_NBX * (M_ALL / BM))          // 6984
#define B_NBX    (IN_DIM / BN)                   // 6
#define B_NBIG   (B_NBX * (M_ALL / BM))          // 1746

#define GBM 64
#define GBN 128
#define GSTG_A (GBM * 128)                       // 8 KB
#define GSTG_B (GBN * 128)                       // 16 KB
#define GSTG (GSTG_A + GSTG_B)                   // 24 KB
#define HM_BLOCKS  (6 * (HID / GBN))             // 144
#define MOE_BLOCKS (ATOMS * 6 * (IN_DIM / GBN))  // 180
#define A_TOTAL (A_NBIG + HM_BLOCKS)             // 7128
#define B_TOTAL (B_NBIG + MOE_BLOCKS)            // 1926

// PHASE 0: big = [hid = gelu(xh@w1t+b1)] ; gather = [hm2 = gelu(cls@wint[a]+b_in)]
// PHASE 1: big = [patch rows -> out store; cls rows -> out += wE0*(v)] ;
//          gather = [out[token] += w*(hm2@woutt[o]+b_out)]
template<int PHASE>
__global__ __launch_bounds__(NTHREADS, 2)
void fused_gemm(const __half* __restrict__ A,
                const __half* __restrict__ Bw,
                const float* __restrict__ bias,
                __half* __restrict__ outH,
                float* __restrict__ outF,
                const float* __restrict__ wE0,
                const __half* __restrict__ Ag,
                const __half* __restrict__ Wsm,
                const float* __restrict__ biasSm,
                __half* __restrict__ outGH,
                float* __restrict__ outGF,
                const int* __restrict__ cnt,
                const int* __restrict__ lst,
                const float* __restrict__ wls)
{
    extern __shared__ char smem[];
    const uint32_t sb = smem_u32(smem);
    const int tid  = threadIdx.x;
    const int wid  = tid >> 5, lane = tid & 31;
    const int NBIG = (PHASE == 0) ? A_NBIG : B_NBIG;
    const int K    = (PHASE == 0) ? IN_DIM : HID;
    const int C    = K >> 6;

    if (blockIdx.x < (unsigned)NBIG) {
        // ---------------- BIG PATH: 128x128 tile, 4 warps 2x2 ----------------
        const int wm = wid >> 1, wn = wid & 1;
        const int bi = blockIdx.x;
        const int NBX = (PHASE == 0) ? A_NBX : B_NBX;
        const int bm = (bi / NBX) * BM;
        const int bn = (bi % NBX) * BN;

        const __half* aG0 = A + (size_t)bm * K;
        const __half* bG0 = Bw + (size_t)bn * K;

        auto loadChunk = [&](int c) {
            const int slot = c % STAGES;
            const uint32_t aS = sb + (uint32_t)slot * (2 * STG_BYTES);
            const uint32_t bS = aS + STG_BYTES;
            const __half* aG = aG0 + c * BK;
            const __half* bG = bG0 + c * BK;
            #pragma unroll
            for (int t = 0; t < 8; t++) {
                int i = t * NTHREADS + tid;
                int row = i >> 3, g = i & 7;
                uint32_t off = (uint32_t)(row * 128 + g * 16);
                cp16(aS + sw128(off), aG + (size_t)row * K + g * 8);
            }
            #pragma unroll
            for (int t = 0; t < 8; t++) {
                int i = t * NTHREADS + tid;
                int row = i >> 3, g = i & 7;
                uint32_t off = (uint32_t)(row * 128 + g * 16);
                cp16(bS + sw128(off), bG + (size_t)row * K + g * 8);
            }
            CP_COMMIT();
        };

        float acc[4][8][4];
        #pragma unroll
        for (int i = 0; i < 4; i++)
            #pragma unroll
            for (int j = 0; j < 8; j++)
                #pragma unroll
                for (int q = 0; q < 4; q++) acc[i][j][q] = 0.0f;

        loadChunk(0);
        loadChunk(1);

        const int aRow = wm * 64 + (lane & 15);
        const int aCol = (lane >> 4) * 16;
        const int bRow = wn * 64 + ((lane >> 4) & 1) * 8 + (lane & 7);
        const int bCol = ((lane >> 3) & 1) * 16;

        for (int c = 0; c < C; c++) {
            if (c + 2 < C) { CP_WAIT(1); } else { CP_WAIT(0); }
            __syncthreads();
            if (c + 2 < C) loadChunk(c + 2);

            const int slot = c % STAGES;
            const uint32_t aS = sb + (uint32_t)slot * (2 * STG_BYTES);
            const uint32_t bS = aS + STG_BYTES;

            #pragma unroll
            for (int kk = 0; kk < 4; kk++) {
                uint32_t af[4][4];
                #pragma unroll
                for (int mt = 0; mt < 4; mt++) {
                    uint32_t off = (uint32_t)((aRow + mt * 16) * 128 + kk * 32 + aCol);
                    ldsm_x4(af[mt][0], af[mt][1], af[mt][2], af[mt][3], aS + sw128(off));
                }
                uint32_t bf[8][2];
                #pragma unroll
                for (int pr = 0; pr < 4; pr++) {
                    uint32_t off = (uint32_t)((bRow + pr * 16) * 128 + kk * 32 + bCol);
                    uint32_t r0, r1, r2, r3;
                    ldsm_x4(r0, r1, r2, r3, bS + sw128(off));
                    bf[pr * 2 + 0][0] = r0; bf[pr * 2 + 0][1] = r1;
                    bf[pr * 2 + 1][0] = r2; bf[pr * 2 + 1][1] = r3;
                }
                #pragma unroll
                for (int mt = 0; mt < 4; mt++)
                    #pragma unroll
                    for (int nt = 0; nt < 8; nt++)
                        mma_f16(acc[mt][nt][0], acc[mt][nt][1], acc[mt][nt][2], acc[mt][nt][3],
                                af[mt][0], af[mt][1], af[mt][2], af[mt][3],
                                bf[nt][0], bf[nt][1]);
            }
        }

        const int q = lane & 3;
        #pragma unroll
        for (int mt = 0; mt < 4; mt++) {
            #pragma unroll
            for (int h = 0; h < 2; h++) {
                const int rowg = bm + wm * 64 + mt * 16 + (lane >> 2) + h * 8;
                __half* rpH = nullptr;
                float*  rpF = nullptr;
                bool  atomCls = false;
                float sc = 1.0f;
                if (PHASE == 0) {
                    rpH = outH + (size_t)rowg * HID;
                } else {
                    if (rowg < M_PATCH) {
                        int bb = rowg / NUM_PATCH, p = rowg - bb * NUM_PATCH;
                        rpF = outF + (size_t)(bb * SEQ + NCLS + p) * IN_DIM;
                    } else {
                        int n = rowg - M_PATCH;
                        int bb = n / NCLS, tt = n - bb * NCLS;
                        rpF = outF + (size_t)(bb * SEQ + tt) * IN_DIM;
                        atomCls = true;
                        sc = wE0[n];
                    }
                }
                #pragma unroll
                for (int nt = 0; nt < 8; nt++) {
                    const int col = bn + wn * 64 + nt * 8 + q * 2;
                    float v0 = acc[mt][nt][h * 2 + 0] + bias[col];
                    float v1 = acc[mt][nt][h * 2 + 1] + bias[col + 1];
                    if (PHASE == 0) {
                        v0 = gelu_f(v0); v1 = gelu_f(v1);
                        __half2 hh; hh.x = __float2half(v0); hh.y = __float2half(v1);
                        *reinterpret_cast<__half2*>(rpH + col) = hh;
                    } else if (atomCls) {
                        atomicAdd(rpF + col,     sc * v0);
                        atomicAdd(rpF + col + 1, sc * v1);
                    } else {
                        *reinterpret_cast<float2*>(rpF + col) = make_float2(v0, v1);
                    }
                }
            }
        }
    } else {
        // ---------------- GATHER PATH: 64x128 tile ----------------
        const int gbi = blockIdx.x - NBIG;
        const int wm = wid >> 1, wn = wid & 1;
        const int N = (PHASE == 0) ? HID : IN_DIM;

        int zsel, mtile, ntile;
        if (PHASE == 0) {
            const int nt = HID / GBN;
            int mslot = gbi / nt; ntile = gbi % nt;
            zsel  = (mslot <= 1) ? 0 : (mslot - 1);
            mtile = (mslot <= 1) ? mslot : 0;
        } else {
            zsel  = gbi / 36;
            int r = gbi % 36;
            mtile = r / 6; ntile = r % 6;
            if (mtile * GBM >= cnt[zsel]) {
                // still participate in the completion ticket
                if (tid == 0) {
                    int tk = atomicAdd(&g_done, 1);
                    if (tk == MOE_BLOCKS - 1) {
                        #pragma unroll
                        for (int a = 0; a < ATOMS; a++) g_cnt[a] = 0;
                        g_done = 0;
                    }
                }
                return;
            }
        }

        if (tid < GBM) {
            const __half* rp; int oi; float w = 1.0f;
            if (PHASE == 0) {
                int r = mtile * GBM + tid;
                int n = (zsel == 0) ? ((r < 64) ? r * 6 : (r - 64) * 6 + 5)
                                    : r * 6 + zsel;
                rp = Ag + (size_t)(M_PATCH + n) * IN_DIM;
                oi = n * HID;                              // hm2 row offset
            } else {
                int r = mtile * GBM + tid;
                if (r < cnt[zsel]) {
                    int e = lst[zsel * M_CLS + r];
                    int n = e & 0xFFFF;
                    rp = Ag + (size_t)n * HID;
                    int bb = n / NCLS, tt = n - bb * NCLS;
                    oi = (bb * SEQ + tt) * IN_DIM;         // out row offset
                    w  = wls[zsel * M_CLS + r];
                } else { rp = Ag; oi = -1; }
            }
            *reinterpret_cast<const __half**>(smem + tid * 8) = rp;
            reinterpret_cast<int*>(smem + 512)[tid]  = oi;
            reinterpret_cast<float*>(smem + 768)[tid] = w;
        }
        __syncthreads();

        const __half* bG0 = Wsm + (size_t)zsel * N * K + (size_t)(ntile * GBN) * K;
        const float* biasZ = biasSm + (size_t)zsel * N;

        auto loadChunkG = [&](int c) {
            const int slot = c % 3;
            const uint32_t aS = sb + 1024u + (uint32_t)slot * GSTG;
            const uint32_t bS = aS + GSTG_A;
            #pragma unroll
            for (int t = 0; t < 4; t++) {
                int i = t * 128 + tid;
                int row = i >> 3, g = i & 7;
                const __half* rp;
                asm("ld.shared.b64 %0, [%1];" : "=l"(rp) : "r"(sb + (uint32_t)(row * 8)));
                uint32_t off = (uint32_t)(row * 128 + g * 16);
                cp16(aS + sw128(off), rp + c * 64 + g * 8);
            }
            const __half* bG = bG0 + c * 64;
            #pragma unroll
            for (int t = 0; t < 8; t++) {
                int i = t * 128 + tid;
                int row = i >> 3, g = i & 7;
                uint32_t off = (uint32_t)(row * 128 + g * 16);
                cp16(bS + sw128(off), bG + (size_t)row * K + g * 8);
            }
            CP_COMMIT();
        };

        float acc[2][8][4];
        #pragma unroll
        for (int i = 0; i < 2; i++)
            #pragma unroll
            for (int j = 0; j < 8; j++)
                #pragma unroll
                for (int q = 0; q < 4; q++) acc[i][j][q] = 0.0f;

        loadChunkG(0);
        loadChunkG(1);

        const int aRow = wm * 32 + (lane & 15);
        const int aCol = (lane >> 4) * 16;
        const int bRow = wn * 64 + ((lane >> 4) & 1) * 8 + (lane & 7);
        const int bCol = ((lane >> 3) & 1) * 16;

        for (int c = 0; c < C; c++) {
            if (c + 2 < C) { CP_WAIT(1); } else { CP_WAIT(0); }
            __syncthreads();
            if (c + 2 < C) loadChunkG(c + 2);

            const int slot = c % 3;
            const uint32_t aS = sb + 1024u + (uint32_t)slot * GSTG;
            const uint32_t bS = aS + GSTG_A;

            #pragma unroll
            for (int kk = 0; kk < 4; kk++) {
                uint32_t af[2][4];
                #pragma unroll
                for (int mt = 0; mt < 2; mt++) {
                    uint32_t off = (uint32_t)((aRow + mt * 16) * 128 + kk * 32 + aCol);
                    ldsm_x4(af[mt][0], af[mt][1], af[mt][2], af[mt][3], aS + sw128(off));
                }
                uint32_t bf[8][2];
                #pragma unroll
                for (int pr = 0; pr < 4; pr++) {
                    uint32_t off = (uint32_t)((bRow + pr * 16) * 128 + kk * 32 + bCol);
                    uint32_t r0, r1, r2, r3;
                    ldsm_x4(r0, r1, r2, r3, bS + sw128(off));
                    bf[pr * 2 + 0][0] = r0; bf[pr * 2 + 0][1] = r1;
                    bf[pr * 2 + 1][0] = r2; bf[pr * 2 + 1][1] = r3;
                }
                #pragma unroll
                for (int mt = 0; mt < 2; mt++)
                    #pragma unroll
                    for (int nt = 0; nt < 8; nt++)
                        mma_f16(acc[mt][nt][0], acc[mt][nt][1], acc[mt][nt][2], acc[mt][nt][3],
                                af[mt][0], af[mt][1], af[mt][2], af[mt][3],
                                bf[nt][0], bf[nt][1]);
            }
        }

        const int q = lane & 3;
        #pragma unroll
        for (int mt = 0; mt < 2; mt++) {
            #pragma unroll
            for (int h = 0; h < 2; h++) {
                const int rowg = wm * 32 + mt * 16 + (lane >> 2) + h * 8;
                int   oi = reinterpret_cast<int*>(smem + 512)[rowg];
                float w  = reinterpret_cast<float*>(smem + 768)[rowg];
                #pragma unroll
                for (int nt = 0; nt < 8; nt++) {
                    const int col = ntile * GBN + wn * 64 + nt * 8 + q * 2;
                    float v0 = acc[mt][nt][h * 2 + 0] + biasZ[col];
                    float v1 = acc[mt][nt][h * 2 + 1] + biasZ[col + 1];
                    if (PHASE == 0) {
                        v0 = gelu_f(v0); v1 = gelu_f(v1);
                        __half2 hh; hh.x = __float2half(v0); hh.y = __float2half(v1);
                        *reinterpret_cast<__half2*>(outGH + (size_t)oi + col) = hh;
                    } else if (oi >= 0) {
                        atomicAdd(outGF + (size_t)oi + col,     w * v0);
                        atomicAdd(outGF + (size_t)oi + col + 1, w * v1);
                    }
                }
            }
        }

        if (PHASE == 1) {
            __syncthreads();
            if (tid == 0) {
                int tk = atomicAdd(&g_done, 1);
                if (tk == MOE_BLOCKS - 1) {
                    #pragma unroll
                    for (int a = 0; a < ATOMS; a++) g_cnt[a] = 0;
                    g_done = 0;
                }
            }
        }
    }
}

// ---------------- fused conversion + gating kernel ----------------
#define CX_BLK   (M_ALL * IN_DIM / 8 / 256)            // 13968 (8 elems/thread)
#define WT_W1    (IN_DIM / 32 * (HID / 32))
#define WT_W2    (HID / 32 * (IN_DIM / 32))
#define WT_WIN   (WT_W1 * ATOMS)
#define WT_WOUT  (WT_W2 * ATOMS)
#define CONV_BLOCKS (CX_BLK + WT_W1 + WT_W2 + WT_WIN + WT_WOUT)
#define CONV_TOTAL (CONV_BLOCKS + M_CLS)

__global__ __launch_bounds__(256)
void conv_all(const float* __restrict__ x,   __half* __restrict__ xh,
              const float* __restrict__ W1,  __half* __restrict__ w1t,
              const float* __restrict__ W2,  __half* __restrict__ w2t,
              const float* __restrict__ Win, __half* __restrict__ wint,
              const float* __restrict__ Wout,__half* __restrict__ woutt,
              const float* __restrict__ Wg,
              int* __restrict__ cnt, int* __restrict__ lst, float* __restrict__ wls,
              float* __restrict__ wE0, float* __restrict__ out)
{
    int bi = blockIdx.x;
    if (bi < CX_BLK) {
        int idx = bi * 256 + threadIdx.x;            // units of 8 elems
        int m  = idx / (IN_DIM / 8);
        int kp = (idx - m * (IN_DIM / 8)) * 8;
        int src;
        if (m < M_PATCH) { int b = m / NUM_PATCH, p = m - b * NUM_PATCH; src = b * SEQ + NCLS + p; }
        else             { int rr = m - M_PATCH; int b = rr / NCLS, t = rr - b * NCLS; src = b * SEQ + t; }
        const float* sp = x + (size_t)src * IN_DIM + kp;
        float4 v0 = *reinterpret_cast<const float4*>(sp);
        float4 v1 = *reinterpret_cast<const float4*>(sp + 4);
        __half2 h0; h0.x = __float2half(v0.x); h0.y = __float2half(v0.y);
        __half2 h1; h1.x = __float2half(v0.z); h1.y = __float2half(v0.w);
        __half2 h2; h2.x = __float2half(v1.x); h2.y = __float2half(v1.y);
        __half2 h3; h3.x = __float2half(v1.z); h3.y = __float2half(v1.w);
        uint4 pk;
        pk.x = *reinterpret_cast<uint32_t*>(&h0);
        pk.y = *reinterpret_cast<uint32_t*>(&h1);
        pk.z = *reinterpret_cast<uint32_t*>(&h2);
        pk.w = *reinterpret_cast<uint32_t*>(&h3);
        *reinterpret_cast<uint4*>(xh + (size_t)m * IN_DIM + kp) = pk;
        return;
    }
    bi -= CX_BLK;

    if (bi >= WT_W1 + WT_W2 + WT_WIN + WT_WOUT) {
        // ---- gating block: one per cls token; also zeroes its out row ----
        const int n = bi - (WT_W1 + WT_W2 + WT_WIN + WT_WOUT);
        const int b = n / NCLS;
        const int t = n - b * NCLS;

        __shared__ float scls[IN_DIM];
        __shared__ float slog[6];

        const float* crow = x + (size_t)(b * SEQ + t) * IN_DIM;
        for (int i = threadIdx.x; i < IN_DIM; i += 256) scls[i] = crow[i];
        // zero the output row this token will accumulate into (phase B)
        {
            float* orow = out + (size_t)(b * SEQ + t) * IN_DIM;
            if (threadIdx.x < IN_DIM / 4) {
                float4 z = make_float4(0.f, 0.f, 0.f, 0.f);
                *reinterpret_cast<float4*>(orow + threadIdx.x * 4) = z;
            }
        }
        __syncthreads();

        const int w = threadIdx.x >> 5, lane = threadIdx.x & 31;
        if (w < 6) {
            const float* wg = Wg + (size_t)t * IN_DIM * 6;
            float s = 0.0f;
            for (int d = lane; d < IN_DIM; d += 32)
                s = fmaf(scls[d], wg[(size_t)d * 6 + w], s);
            #pragma unroll
            for (int off = 16; off > 0; off >>= 1)
                s += __shfl_down_sync(0xffffffffu, s, off);
            if (lane == 0) slog[w] = s;
        }
        __syncthreads();

        if (threadIdx.x == 0) {
            float l[6];
            #pragma unroll
            for (int j = 0; j < 6; j++) l[j] = slog[j];
            int i0 = 0;
            #pragma unroll
            for (int j = 1; j < 6; j++) if (l[j] > l[i0]) i0 = j;
            int i1 = (i0 == 0) ? 1 : 0;
            #pragma unroll
            for (int j = 0; j < 6; j++) if (j != i0 && l[j] > l[i1]) i1 = j;
            float p1 = expf(l[i1] - l[i0]);
            float inv = 1.0f / (1.0f + p1);
            float w0 = inv, w1 = p1 * inv;
            wE0[n] = ((i0 == 0) ? w0 : 0.0f) + ((i1 == 0) ? w1 : 0.0f);
            if (i0 > 0) {
                int idx = atomicAdd(&cnt[i0 - 1], 1);
                lst[(i0 - 1) * M_CLS + idx] = n;
                wls[(i0 - 1) * M_CLS + idx] = w0;
            }
            if (i1 > 0) {
                int idx = atomicAdd(&cnt[i1 - 1], 1);
                lst[(i1 - 1) * M_CLS + idx] = n;
                wls[(i1 - 1) * M_CLS + idx] = w1;
            }
        }
        return;
    }

    const float* W; __half* Wt; int K, N, tileIdx;
    if (bi < WT_W1)                   { W = W1;  Wt = w1t;  K = IN_DIM; N = HID;    tileIdx = bi; }
    else if ((bi -= WT_W1)  < WT_W2)  { W = W2;  Wt = w2t;  K = HID;    N = IN_DIM; tileIdx = bi; }
    else if ((bi -= WT_W2)  < WT_WIN) {
        int z = bi / WT_W1; tileIdx = bi - z * WT_W1;
        W = Win  + (size_t)z * IN_DIM * HID; Wt = wint  + (size_t)z * HID * IN_DIM;
        K = IN_DIM; N = HID;
    } else {
        bi -= WT_WIN;
        int z = bi / WT_W2; tileIdx = bi - z * WT_W2;
        W = Wout + (size_t)z * HID * IN_DIM; Wt = woutt + (size_t)z * IN_DIM * HID;
        K = HID; N = IN_DIM;
    }

    __shared__ float t[32][33];
    const int ktiles = K / 32;
    int k0 = (tileIdx % ktiles) * 32, n0 = (tileIdx / ktiles) * 32;
    int tx = threadIdx.x & 31, ty = threadIdx.x >> 5;
    #pragma unroll
    for (int i = 0; i < 4; i++)
        t[ty + i * 8][tx] = W[(size_t)(k0 + ty + i * 8) * N + n0 + tx];
    __syncthreads();
    #pragma unroll
    for (int it = 0; it < 2; it++) {
        int item = it * 256 + threadIdx.x;
        int n  = n0 + (item >> 4);
        int kp = (item & 15) * 2;
        __half2 hv;
        hv.x = __float2half(t[kp][item >> 4]);
        hv.y = __float2half(t[kp + 1][item >> 4]);
        *reinterpret_cast<__half2*>(Wt + (size_t)n * K + k0 + kp) = hv;
    }
}

// ---------------- launch ----------------
extern "C" void kernel_launch(void* const* d_in, const int* in_sizes, int n_in,
                              void* d_out, int out_size)
{
    const float* x     = (const float*)d_in[0];
    const float* W1    = (const float*)d_in[1];
    const float* b1    = (const float*)d_in[2];
    const float* W2    = (const float*)d_in[3];
    const float* b2    = (const float*)d_in[4];
    const float* W_in  = (const float*)d_in[5];
    const float* b_in  = (const float*)d_in[6];
    const float* W_out = (const float*)d_in[7];
    const float* b_out = (const float*)d_in[8];
    const float* Wg    = (const float*)d_in[9];
    float* out = (float*)d_out;

    static __half *xh = nullptr, *w1t, *hid, *w2t, *wint, *woutt, *hm2;
    static float *wls, *wE0;
    static int *cnt, *lst;
    if (!xh) {
        cudaGetSymbolAddress((void**)&xh,    g_xh);
        cudaGetSymbolAddress((void**)&w1t,   g_w1t);
        cudaGetSymbolAddress((void**)&hid,   g_hid);
        cudaGetSymbolAddress((void**)&w2t,   g_w2t);
        cudaGetSymbolAddress((void**)&wint,  g_wint);
        cudaGetSymbolAddress((void**)&woutt, g_woutt);
        cudaGetSymbolAddress((void**)&hm2,   g_hm2);
        cudaGetSymbolAddress((void**)&cnt,   g_cnt);
        cudaGetSymbolAddress((void**)&lst,   g_lst);
        cudaGetSymbolAddress((void**)&wls,   g_wls);
        cudaGetSymbolAddress((void**)&wE0,   g_wE0);
        cudaFuncSetAttribute((const void*)fused_gemm<0>,
                             cudaFuncAttributeMaxDynamicSharedMemorySize, SMEM_DYN);
        cudaFuncSetAttribute((const void*)fused_gemm<1>,
                             cudaFuncAttributeMaxDynamicSharedMemorySize, SMEM_DYN);
    }

    // 1: conversions + gating + cls-row zeroing (cnt is 0 on entry)
    conv_all<<<CONV_TOTAL, 256>>>(x, xh, W1, w1t, W2, w2t, W_in, wint, W_out, woutt,
                                  Wg, cnt, lst, wls, wE0, out);

    // 2: phase A big GEMM + hm2 gather tiles
    fused_gemm<0><<<A_TOTAL, NTHREADS, SMEM_DYN>>>(
        xh, w1t, b1, hid, nullptr, nullptr,
        xh, wint, b_in, hm2, nullptr, cnt, lst, wls);

    // 3: phase B big GEMM (patch store, cls accumulate) + moeOut gather accumulate
    fused_gemm<1><<<B_TOTAL, NTHREADS, SMEM_DYN>>>(
        hid, w2t, b2, nullptr, out, wE0,
        hm2, woutt, b_out, nullptr, out, cnt, lst, wls);
}